// round 17
// baseline (speedup 1.0000x reference)
#include <cuda_runtime.h>
#include <cstdint>

// Shape fixed by dataset: B=16, T=8192, N=32, depth=31.
constexpr int N_STACK = 32;
constexpr int DEPTH   = 31;
constexpr int OPSROW  = DEPTH * 5;       // 155 floats per (b,t) row
constexpr int TPB     = 64;
constexpr int LPAD    = 33;              // log row stride (odd -> conflict-free scalar LDS)
constexpr int SSTRIDE = 20;              // ops chunk row stride in floats (80B, LDS.128 conflict-free)
constexpr int BT_TOTAL = 131072;
constexpr int QMAX = (BT_TOTAL * OPSROW) / 4 - 1;   // last valid float4 index in ops

// (1/(32-k)) * 0.01  — scale = rsqrt(max((SS+nlog^2)*CS_INV01[k] + 1e-8, 1))
__constant__ float CS_INV01[DEPTH] = {
    0.01f/32, 0.01f/31, 0.01f/30, 0.01f/29, 0.01f/28, 0.01f/27, 0.01f/26, 0.01f/25,
    0.01f/24, 0.01f/23, 0.01f/22, 0.01f/21, 0.01f/20, 0.01f/19, 0.01f/18, 0.01f/17,
    0.01f/16, 0.01f/15, 0.01f/14, 0.01f/13, 0.01f/12, 0.01f/11, 0.01f/10, 0.01f/9,
    0.01f/8,  0.01f/7,  0.01f/6,  0.01f/5,  0.01f/4,  0.01f/3,  0.01f/2 };

__device__ __forceinline__ float tanh_ap(float x) {
    float r;
    asm("tanh.approx.f32 %0, %1;" : "=f"(r) : "f"(x));
    return r;
}
__device__ __forceinline__ float tanh10(float x) {   // 10*tanh(x/10)
    return 10.0f * tanh_ap(x * 0.1f);
}

struct State { float rs, rl, SS; };

// One soft-op step. sec = original stack entry; top = running (st.rs, st.rl).
__device__ __forceinline__ void do_step(int k, const float* lrow, unsigned smask,
                                        float p0, float p1, float p2, float p3, float p4,
                                        State& st) {
    int   si = 30 - k;
    float sl = lrow[si];                                   // scalar LDS, conflict-free
    float ss = __uint_as_float(0x3F800000u | ((smask << (31 - si)) & 0x80000000u));
    float rs = st.rs, rl = st.rl;

    float mx  = fmaxf(sl, rl), mn = fminf(sl, rl);
    float ed  = __expf(mn - mx);                           // e^{mn-mx} in (0,1]
    float lse = mx + __logf(1.0f + ed);
    float C1  = 10.0f * tanh_ap(tanh_ap(lse * 0.1f));      // same-sign: double clip (as ref)
    float edc  = fminf(fmaxf(ed, 4.5399930e-5f), 0.99900050f);
    float diff = __logf(1.0f - edc);
    bool  zr   = (mn == mx);
    float C2   = zr ? 0.0f : tanh10(mx + diff);            // opposite-sign: single clip

    bool  bx   = (sl >= rl);
    float srs  = ss * rs;
    bool  same = (srs > 0.0f);
    float bsA  = bx ? ss : rs;
    float bsS  = bx ? ss : -rs;

    float aS, aL, sS, sL;
    if (same) { aS = ss;               aL = C1;  sS = zr ? 0.0f : bsS;  sL = C2; }
    else      { aS = zr ? 0.0f : bsA;  aL = C2;  sS = ss;               sL = C1; }

    float mulL = tanh10(sl + rl);
    float divL = tanh10(sl - rl);

    float nsgn = aS * p0 + sS * p1 + srs * (p2 + p3) + ss * p4;
    float nlog = aL * p0 + sL * p1 + mulL * p2 + divL * p3 + sl * p4;

    float m01   = fmaf(fmaf(nlog, nlog, st.SS), CS_INV01[k], 1e-8f);
    float scale = rsqrtf(fmaxf(m01, 1.0f));

    st.rl = nlog * scale;
    st.rs = nsgn;
    st.SS = fmaf(-sl, sl, st.SS);
}

__device__ __forceinline__ float comp(const float4& v, int j) {
    return j == 0 ? v.x : j == 1 ? v.y : j == 2 ? v.z : v.w;
}
// Chunk element E (0..19) from the 5 consumed quads.
template<int E>
__device__ __forceinline__ float pf(const float4& f0, const float4& f1, const float4& f2,
                                    const float4& f3, const float4& f4) {
    constexpr int q = E / 4, j = E % 4;
    if constexpr (q == 0) return comp(f0, j);
    else if constexpr (q == 1) return comp(f1, j);
    else if constexpr (q == 2) return comp(f2, j);
    else if constexpr (q == 3) return comp(f3, j);
    else return comp(f4, j);
}

// ---- warp-cooperative ops chunk producer (quad granularity) ----
// Chunk = 20 floats [F0, F0+20) of each of the warp's 32 rows (rows contiguous).
// NQ aligned quads per row cover the span for any per-row alignment O=(row*155)&3.
template<int NQ>
__device__ __forceinline__ void chunk_load(float4* pv, const float4* __restrict__ ops4,
                                           int warpBase, int F0, int lane) {
#pragma unroll
    for (int i = 0; i < NQ; i++) {
        int idx = i * 32 + lane;
        int row = idx / NQ;                  // compile-time divisor
        int jq  = idx - row * NQ;
        int Fb  = (warpBase + row) * OPSROW + F0;
        int q   = (Fb >> 2) + jq;
        q = q < QMAX ? q : QMAX;             // array-end clamp (affects only unused tail)
        pv[i] = __ldg(ops4 + q);
    }
}
template<int NQ>
__device__ __forceinline__ void chunk_store(const float4* pv, float* sbuf,
                                            int warpBase, int F0, int lane) {
#pragma unroll
    for (int i = 0; i < NQ; i++) {
        int idx = i * 32 + lane;
        int row = idx / NQ;
        int jq  = idx - row * NQ;
        int O   = ((warpBase + row) * OPSROW + F0) & 3;
        int p0  = 4 * jq - O;                // rebased chunk position of pv[i].x
        float* dst = sbuf + row * SSTRIDE;
        if ((unsigned)(p0 + 0) < 20u) dst[p0 + 0] = pv[i].x;
        if ((unsigned)(p0 + 1) < 20u) dst[p0 + 1] = pv[i].y;
        if ((unsigned)(p0 + 2) < 20u) dst[p0 + 2] = pv[i].z;
        if ((unsigned)(p0 + 3) < 20u) dst[p0 + 3] = pv[i].w;
    }
}

__global__ __launch_bounds__(TPB, 11)
void stack_machine_kernel(const float* __restrict__ sgn,
                          const float* __restrict__ logm,
                          const float* __restrict__ ops,
                          float* __restrict__ out,
                          int bt_total) {
    __shared__ float LBUF[TPB * LPAD];
    __shared__ float SBUF[2][32 * SSTRIDE];   // one chunk buffer per warp

    const int tid  = threadIdx.x;
    const int lane = tid & 31;
    const int w    = tid >> 5;
    const int warpBase = blockIdx.x * TPB + w * 32;   // warp's 32 contiguous chains
    const int bt   = warpBase + lane;
    float* lrow = LBUF + tid * LPAD;
    float* sbuf = SBUF[w];
    const float4* ops4 = reinterpret_cast<const float4*>(ops);

    // ---- kick chunk-0 ops loads first (deepest latency) ----
    float4 pv[6];
    chunk_load<6>(pv, ops4, warpBase, 0, lane);

    // ---- logm: fully-coalesced float4 loads -> transposed into LBUF ----
    {
        const float4* gl4 = reinterpret_cast<const float4*>(logm) + (size_t)warpBase * 8;
        float* wbuf = LBUF + (w * 32) * LPAD;
#pragma unroll
        for (int it = 0; it < 8; it++) {
            int lin = it * 32 + lane;
            float4 v = __ldg(gl4 + lin);
            int row = lin >> 3, f4c = lin & 7;
            float* dst = wbuf + row * LPAD + f4c * 4;
            dst[0] = v.x; dst[1] = v.y; dst[2] = v.z; dst[3] = v.w;
        }
    }

    // ---- sgn: coalesced row loads + ballot -> per-thread sign bitmask ----
    unsigned smask = 0;
#pragma unroll
    for (int it = 0; it < 32; it++) {
        float f = __ldg(sgn + (size_t)(warpBase + it) * N_STACK + lane);
        unsigned m = __ballot_sync(0xffffffffu, f < 0.0f);
        if (lane == it) smask = m;
    }
    __syncwarp();

    // ---- suffix sum-of-squares over original logs 0..30 ----
    State st;
    st.SS = 0.0f;
#pragma unroll
    for (int i = 0; i < N_STACK - 1; i++) st.SS = fmaf(lrow[i], lrow[i], st.SS);
    st.rl = lrow[N_STACK - 1];
    st.rs = (smask >> 31) & 1u ? -1.0f : 1.0f;

    // ---- chunk 0 into smem, consume to regs, start chunk 1 ----
    chunk_store<6>(pv, sbuf, warpBase, 0, lane);
    __syncwarp();
    const float4* srow = reinterpret_cast<const float4*>(sbuf + lane * SSTRIDE);
    float4 f0 = srow[0], f1 = srow[1], f2 = srow[2], f3 = srow[3], f4 = srow[4];
    chunk_load<6>(pv, ops4, warpBase, 20, lane);

    // ---- 7 groups x 4 steps; single smem buffer, warp-synchronous pipeline ----
#pragma unroll 1
    for (int g = 0; g < 7; g++) {
        int k0 = 4 * g;
        do_step(k0 + 0, lrow, smask, pf< 0>(f0,f1,f2,f3,f4), pf< 1>(f0,f1,f2,f3,f4),
                pf< 2>(f0,f1,f2,f3,f4), pf< 3>(f0,f1,f2,f3,f4), pf< 4>(f0,f1,f2,f3,f4), st);
        do_step(k0 + 1, lrow, smask, pf< 5>(f0,f1,f2,f3,f4), pf< 6>(f0,f1,f2,f3,f4),
                pf< 7>(f0,f1,f2,f3,f4), pf< 8>(f0,f1,f2,f3,f4), pf< 9>(f0,f1,f2,f3,f4), st);
        do_step(k0 + 2, lrow, smask, pf<10>(f0,f1,f2,f3,f4), pf<11>(f0,f1,f2,f3,f4),
                pf<12>(f0,f1,f2,f3,f4), pf<13>(f0,f1,f2,f3,f4), pf<14>(f0,f1,f2,f3,f4), st);
        do_step(k0 + 3, lrow, smask, pf<15>(f0,f1,f2,f3,f4), pf<16>(f0,f1,f2,f3,f4),
                pf<17>(f0,f1,f2,f3,f4), pf<18>(f0,f1,f2,f3,f4), pf<19>(f0,f1,f2,f3,f4), st);

        // stage chunk g+1 (values arrived during the ~540-cyc compute above)
        if (g < 6) {
            chunk_store<6>(pv, sbuf, warpBase, 20 * (g + 1), lane);
            __syncwarp();
            f0 = srow[0]; f1 = srow[1]; f2 = srow[2]; f3 = srow[3]; f4 = srow[4];
            if (g < 5)      chunk_load<6>(pv, ops4, warpBase, 20 * (g + 2), lane);
            else            chunk_load<5>(pv, ops4, warpBase, 140, lane);  // epilogue: 15 floats
        } else {
            chunk_store<5>(pv, sbuf, warpBase, 140, lane);
            __syncwarp();
            f0 = srow[0]; f1 = srow[1]; f2 = srow[2]; f3 = srow[3];        // 16 >= 15 floats
        }
    }

    // ---- epilogue: steps 28..30 (chunk floats 0..14) ----
    do_step(28, lrow, smask, pf< 0>(f0,f1,f2,f3,f4), pf< 1>(f0,f1,f2,f3,f4),
            pf< 2>(f0,f1,f2,f3,f4), pf< 3>(f0,f1,f2,f3,f4), pf< 4>(f0,f1,f2,f3,f4), st);
    do_step(29, lrow, smask, pf< 5>(f0,f1,f2,f3,f4), pf< 6>(f0,f1,f2,f3,f4),
            pf< 7>(f0,f1,f2,f3,f4), pf< 8>(f0,f1,f2,f3,f4), pf< 9>(f0,f1,f2,f3,f4), st);
    do_step(30, lrow, smask, pf<10>(f0,f1,f2,f3,f4), pf<11>(f0,f1,f2,f3,f4),
            pf<12>(f0,f1,f2,f3,f4), pf<13>(f0,f1,f2,f3,f4), pf<14>(f0,f1,f2,f3,f4), st);

    out[bt]            = st.rs;   // (sign, log) stacked -> (2, B*T); coalesced
    out[bt_total + bt] = st.rl;
}

extern "C" void kernel_launch(void* const* d_in, const int* in_sizes, int n_in,
                              void* d_out, int out_size) {
    const float* sgn  = (const float*)d_in[0];
    const float* logm = (const float*)d_in[1];
    const float* ops  = (const float*)d_in[2];
    float* out = (float*)d_out;

    int bt_total = out_size / 2;                 // 131072; divisible by TPB
    int blocks = bt_total / TPB;                 // 2048
    stack_machine_kernel<<<blocks, TPB>>>(sgn, logm, ops, out, bt_total);
}